// round 11
// baseline (speedup 1.0000x reference)
#include <cuda_runtime.h>

// DotProcessorBlock: feat = x*w + b (per row, N=256)
// out[b, k] = feat[k>>8] * feat[k&255] for k in [0, 32896)
// B=4096 rows, ~539 MB of pure f32 stores -> HBM-write-bound.
// R11 (final form): proven-best shape — CHUNKS=16, BLOCK=256, barrier-free
// prologue, streaming stores. Micro-tweak vs R7: both fi loads issued up
// front so the two STG.128 are fully independent (max MLP).
// Timed-loop BW ~7.27 TB/s = 91% of 8 TB/s spec: at the practical write floor.

#define N_FEAT 256
#define NUM_OUT 32896                 // N*(N+1)/2
#define OUT_VEC4 (NUM_OUT / 4)        // 8224 float4 per row
#define CHUNKS 16
#define CHUNK_V4 (OUT_VEC4 / CHUNKS)  // 514 float4 per chunk = 2*256 + 2

__global__ __launch_bounds__(256, 8)
void dot_outer_kernel(const float* __restrict__ x,
                      const float* __restrict__ w,
                      const float* __restrict__ bias,
                      float* __restrict__ out)
{
    const int row   = blockIdx.x >> 4;          // / CHUNKS
    const int chunk = blockIdx.x & (CHUNKS - 1);
    const int tid   = threadIdx.x;

    const int t0 = chunk * CHUNK_V4 + tid;
    const int t1 = t0 + 256;
    const int j  = t0 & 63;                     // float4 column, invariant under +256/+512

    const float4* __restrict__ x4 = reinterpret_cast<const float4*>(x) + (size_t)row * (N_FEAT / 4);
    const float4* __restrict__ w4 = reinterpret_cast<const float4*>(w);
    const float4* __restrict__ b4 = reinterpret_cast<const float4*>(bias);
    const float*  __restrict__ xr = x + (size_t)row * N_FEAT;

    // Batch ALL loads first: 3x LDG.128 for fj, plus both iterations'
    // near-warp-uniform scalar operands (L1/L2-hot). Max MLP, no barrier.
    const float4 xa = x4[j];
    const float4 wa = w4[j];
    const float4 ba = b4[j];

    const int i0 = t0 >> 6;
    const int i1 = t1 >> 6;
    const float xi0 = xr[i0], wi0 = w[i0], bi0 = bias[i0];
    const float xi1 = xr[i1], wi1 = w[i1], bi1 = bias[i1];

    float4 fj;
    fj.x = fmaf(xa.x, wa.x, ba.x);
    fj.y = fmaf(xa.y, wa.y, ba.y);
    fj.z = fmaf(xa.z, wa.z, ba.z);
    fj.w = fmaf(xa.w, wa.w, ba.w);

    const float fi0 = fmaf(xi0, wi0, bi0);
    const float fi1 = fmaf(xi1, wi1, bi1);

    float4* __restrict__ out4 = reinterpret_cast<float4*>(out) + (size_t)row * OUT_VEC4;

    float4 v0 = { fj.x * fi0, fj.y * fi0, fj.z * fi0, fj.w * fi0 };
    float4 v1 = { fj.x * fi1, fj.y * fi1, fj.z * fi1, fj.w * fi1 };
    __stcs(&out4[t0], v0);
    __stcs(&out4[t1], v1);

    // 2-element tail (threads 0..1); fj index unchanged since 512 % 64 == 0
    if (tid < (CHUNK_V4 - 2 * 256)) {
        const int t2 = t0 + 512;
        const int i2 = t2 >> 6;
        const float fi2 = fmaf(xr[i2], w[i2], bias[i2]);
        float4 v2 = { fj.x * fi2, fj.y * fi2, fj.z * fi2, fj.w * fi2 };
        __stcs(&out4[t2], v2);
    }
}

extern "C" void kernel_launch(void* const* d_in, const int* in_sizes, int n_in,
                              void* d_out, int out_size)
{
    const float* x    = (const float*)d_in[0];
    const float* w    = (const float*)d_in[1];
    const float* bias = (const float*)d_in[2];
    float* out        = (float*)d_out;

    const int B = in_sizes[0] / N_FEAT;   // 4096
    dot_outer_kernel<<<B * CHUNKS, 256>>>(x, w, bias, out);
}

// round 12
// speedup vs baseline: 1.0548x; 1.0548x over previous
#include <cuda_runtime.h>

// DotProcessorBlock: feat = x*w + b (per row, N=256)
// out[b, k] = feat[k>>8] * feat[k&255] for k in [0, 32896)
// B=4096 rows, ~539 MB of pure f32 stores -> HBM-write-bound.
// FINAL (== R7, measured 74.18us, ~7.27 TB/s = 91% of HBM spec):
//   - CHUNKS=16, BLOCK=256: best quantum on the measured curve (8/16/32 ->
//     74.9/74.2/98.4 us); drain tail minimized without starving store ILP.
//   - Barrier-free prologue: each warp computes fj (its float4 of feat) and
//     per-iteration fi (near-warp-uniform, L1/L2-hot) straight from global;
//     no smem, no BAR, stores issue as soon as each store's OWN operands land
//     (batching all loads first regressed to 78.2us in R11).
//   - __stcs streaming stores: output is never re-read (+2.7us vs default).

#define N_FEAT 256
#define NUM_OUT 32896                 // N*(N+1)/2
#define OUT_VEC4 (NUM_OUT / 4)        // 8224 float4 per row
#define CHUNKS 16
#define CHUNK_V4 (OUT_VEC4 / CHUNKS)  // 514 float4 per chunk = 2*256 + 2

__global__ __launch_bounds__(256, 8)
void dot_outer_kernel(const float* __restrict__ x,
                      const float* __restrict__ w,
                      const float* __restrict__ bias,
                      float* __restrict__ out)
{
    const int row   = blockIdx.x >> 4;          // / CHUNKS
    const int chunk = blockIdx.x & (CHUNKS - 1);
    const int tid   = threadIdx.x;

    const int t0 = chunk * CHUNK_V4 + tid;
    const int j  = t0 & 63;                     // float4 column, invariant under t += 256
                                                // (tail +512: 512 % 64 == 0, still invariant)

    const float4* __restrict__ x4 = reinterpret_cast<const float4*>(x) + (size_t)row * (N_FEAT / 4);
    const float4* __restrict__ w4 = reinterpret_cast<const float4*>(w);
    const float4* __restrict__ b4 = reinterpret_cast<const float4*>(bias);

    // fj = feat[4j..4j+3] in registers (no smem, no barrier, warp-private latency)
    const float4 xa = x4[j];
    const float4 wa = w4[j];
    const float4 ba = b4[j];
    float4 fj;
    fj.x = fmaf(xa.x, wa.x, ba.x);
    fj.y = fmaf(xa.y, wa.y, ba.y);
    fj.z = fmaf(xa.z, wa.z, ba.z);
    fj.w = fmaf(xa.w, wa.w, ba.w);

    const float* __restrict__ xr = x + (size_t)row * N_FEAT;
    float4* __restrict__ out4 = reinterpret_cast<float4*>(out) + (size_t)row * OUT_VEC4;

    // Iteration 0 and 1 (always in range: CHUNK_V4 = 2*256 + 2)
    {
        const int i = t0 >> 6;                  // fi index, near-uniform per warp
        const float fi = fmaf(xr[i], w[i], bias[i]);
        float4 v = { fj.x * fi, fj.y * fi, fj.z * fi, fj.w * fi };
        __stcs(&out4[t0], v);
    }
    {
        const int t1 = t0 + 256;
        const int i = t1 >> 6;
        const float fi = fmaf(xr[i], w[i], bias[i]);
        float4 v = { fj.x * fi, fj.y * fi, fj.z * fi, fj.w * fi };
        __stcs(&out4[t1], v);
    }
    // 2-element tail (threads 0..1); fj index unchanged since 512 % 64 == 0
    if (tid < (CHUNK_V4 - 2 * 256)) {
        const int t2 = t0 + 512;
        const int i = t2 >> 6;
        const float fi = fmaf(xr[i], w[i], bias[i]);
        float4 v = { fj.x * fi, fj.y * fi, fj.z * fi, fj.w * fi };
        __stcs(&out4[t2], v);
    }
}

extern "C" void kernel_launch(void* const* d_in, const int* in_sizes, int n_in,
                              void* d_out, int out_size)
{
    const float* x    = (const float*)d_in[0];
    const float* w    = (const float*)d_in[1];
    const float* bias = (const float*)d_in[2];
    float* out        = (float*)d_out;

    const int B = in_sizes[0] / N_FEAT;   // 4096
    dot_outer_kernel<<<B * CHUNKS, 256>>>(x, w, bias, out);
}